// round 14
// baseline (speedup 1.0000x reference)
#include <cuda_runtime.h>
#include <cstdint>

// StratifiedRaysampler — FINAL champion (converged at HW write roofline):
//   z_j = 0.1 + j * (5.9/127),  j in [0,128)
//   points[i,j,c]  = z_j * directions[i,c] / directions[i,2]
//   lengths[i,j,0] = z_j
// d_out layout: [points (N_RAYS*128*3 f32)] ++ [lengths (N_RAYS*128 f32)]
//
// Converged over 13 rounds of A/B on GB300; 74.46-74.50us reproducible x4.
//  * fused single kernel (2-kernel split: +21us).
//  * 1 ray per warp, block=128 — regs 24, occ ~90%. Coarsening x2/x4
//    regressed (regs 37/40 -> occ ~66%); block=512 regressed; 256 ties.
//  * ALL stores STG.128 .cs: every L2::cache_hint policy variant (evict_last
//    full/96MB-subset, default lengths) kept DRAM bytes identical
//    (~475MB/replay) but degraded writeback ordering: +5..12% regression.
//  * lengths float4 first, then contiguous 3x STG.128 points burst per warp.
//  * Isolated writeback 6.27-6.31 TB/s = the measured LTS chip cap
//    (~6300 B/cyc); duration is set purely by the 537MB mandatory output
//    stream (+~58MB/replay free L2 absorption). Roofline reached.

#define N_PTS 128
#define MIN_DEPTH 0.1f
#define Z_STEP (5.9f / 127.0f)

__global__ void __launch_bounds__(128) fused_raysampler_kernel(
    const float* __restrict__ dirs,
    float* __restrict__ points_out,
    float* __restrict__ lengths_out,
    unsigned n_rays)
{
    unsigned gtid = blockIdx.x * blockDim.x + threadIdx.x;
    unsigned ray  = gtid >> 5;
    unsigned lane = gtid & 31u;
    if (ray >= n_rays) return;

    unsigned l4 = 4u * lane;

    // lengths first: lane l -> z values [4l, 4l+3]
    {
        float jb = (float)l4;
        float4 lv;
        lv.x = __fmaf_rn(jb + 0.0f, Z_STEP, MIN_DEPTH);
        lv.y = __fmaf_rn(jb + 1.0f, Z_STEP, MIN_DEPTH);
        lv.z = __fmaf_rn(jb + 2.0f, Z_STEP, MIN_DEPTH);
        lv.w = __fmaf_rn(jb + 3.0f, Z_STEP, MIN_DEPTH);
        __stcs(reinterpret_cast<float4*>(lengths_out) + (size_t)ray * 32u + lane, lv);
    }

    // Warp-uniform loads (single wavefront each, L1 broadcast)
    float d0 = __ldg(&dirs[ray * 3u + 0u]);
    float d1 = __ldg(&dirs[ray * 3u + 1u]);
    float d2 = __ldg(&dirs[ray * 3u + 2u]);
    float inv = 1.0f / d2;
    float s0 = d0 * inv;
    float s1 = d1 * inv;
    float t0 = Z_STEP * s0;     // delta of za*s0 when j -> j+1
    float t1 = Z_STEP * s1;

    float4* pbase = reinterpret_cast<float4*>(points_out + (size_t)ray * 384u);

    float4 vv[3];
#pragma unroll
    for (unsigned k = 0; k < 3; ++k) {
        unsigned e0 = l4 + 128u * k;      // element index within ray
        unsigned j  = e0 / 3u;            // strength-reduced (IMAD.HI)
        unsigned c0 = e0 - 3u * j;        // {0,1,2}

        float za = __fmaf_rn((float)j, Z_STEP, MIN_DEPTH);
        float zb = za + Z_STEP;

        // 4 consecutive elements span at most two z values:
        // p[] = {za*s0, za*s1, za, zb*s0, zb*s1, zb}; out[m] = p[c0+m]
        float p0 = za * s0;
        float p1 = za * s1;
        float p2 = za;
        float p3 = p0 + t0;               // zb*s0
        float p4 = p1 + t1;               // zb*s1
        float p5 = zb;

        bool c1 = (c0 == 1u);
        bool c2 = (c0 == 2u);
        vv[k].x = c2 ? p2 : (c1 ? p1 : p0);
        vv[k].y = c2 ? p3 : (c1 ? p2 : p1);
        vv[k].z = c2 ? p4 : (c1 ? p3 : p2);
        vv[k].w = c2 ? p5 : (c1 ? p4 : p3);
    }

    // Back-to-back contiguous point stores: warp covers its full 1536B ray.
    __stcs(pbase + lane,       vv[0]);
    __stcs(pbase + 32u + lane, vv[1]);
    __stcs(pbase + 64u + lane, vv[2]);
}

extern "C" void kernel_launch(void* const* d_in, const int* in_sizes, int n_in,
                              void* d_out, int out_size) {
    // inputs: [0] origins (unused), [1] directions
    const float* dirs = (const float*)d_in[1];
    float* out = (float*)d_out;

    unsigned n_rays = (unsigned)(in_sizes[1] / 3);            // 262144
    size_t points_elems = (size_t)n_rays * N_PTS * 3;         // 100663296
    float* lengths_out = out + points_elems;

    unsigned threads = 128;                                   // 4 warps = 4 rays/block
    unsigned blocks = (n_rays * 32u + threads - 1) / threads; // 65536
    fused_raysampler_kernel<<<blocks, threads>>>(dirs, out, lengths_out, n_rays);
}